// round 3
// baseline (speedup 1.0000x reference)
#include <cuda_runtime.h>
#include <math.h>
#include <stdint.h>

#define NN 50000
#define NE 640000
#define RR 8
#define DD 128
#define NRSEG (NN*RR)
#define NBLK ((NRSEG + 1023)/1024)

// ---------------- scratch (device globals; no allocations allowed) ----------
__device__ int   g_cnt[NRSEG];
__device__ int   g_off[NRSEG];
__device__ int   g_cur[NRSEG];
__device__ int   g_bsum[NBLK];
__device__ int   g_srcs[NE];
__device__ int   g_dstn[NE];
__device__ float g_einv[NE];
__device__ float g_h[NN*DD];
__device__ float g_Wt1[(RR+1)*DD*DD];   // [chunk][n][k], chunk 8 = root
__device__ float g_Wt2[(RR+1)*64*DD];

// ---------------- CSR build: histogram -> scan -> scatter -------------------
// seg ordering is RELATION-MAJOR: seg = rel*NN + node, so each (tile, rel)
// owns one contiguous edge slice.
__global__ void k_zero() {
    int i = blockIdx.x*blockDim.x + threadIdx.x;
    if (i < NRSEG) g_cnt[i] = 0;
}

__global__ void k_hist(const int* __restrict__ dst, const int* __restrict__ typ) {
    int e = blockIdx.x*blockDim.x + threadIdx.x;
    if (e < NE) atomicAdd(&g_cnt[typ[e]*NN + dst[e]], 1);
}

__global__ void k_scan1() {
    __shared__ int s[1024];
    int tid = threadIdx.x;
    int i = blockIdx.x*1024 + tid;
    int v = (i < NRSEG) ? g_cnt[i] : 0;
    s[tid] = v; __syncthreads();
    for (int d = 1; d < 1024; d <<= 1) {
        int t = (tid >= d) ? s[tid-d] : 0;
        __syncthreads();
        s[tid] += t;
        __syncthreads();
    }
    if (i < NRSEG) g_off[i] = s[tid] - v;
    if (tid == 1023) g_bsum[blockIdx.x] = s[1023];
}

__global__ void k_scan2() {
    __shared__ int s[512];
    int tid = threadIdx.x;
    int v = (tid < NBLK) ? g_bsum[tid] : 0;
    s[tid] = v; __syncthreads();
    for (int d = 1; d < 512; d <<= 1) {
        int t = (tid >= d) ? s[tid-d] : 0;
        __syncthreads();
        s[tid] += t;
        __syncthreads();
    }
    if (tid < NBLK) g_bsum[tid] = s[tid] - v;
}

__global__ void k_scan3() {
    int i = blockIdx.x*blockDim.x + threadIdx.x;
    if (i < NRSEG) {
        int o = g_off[i] + g_bsum[i >> 10];
        g_off[i] = o;
        g_cur[i] = o;
    }
}

__global__ void k_scatter(const int* __restrict__ src, const int* __restrict__ dst,
                          const int* __restrict__ typ) {
    int e = blockIdx.x*blockDim.x + threadIdx.x;
    if (e < NE) {
        int d = dst[e];
        int seg = typ[e]*NN + d;
        int pos = atomicAdd(&g_cur[seg], 1);
        g_srcs[pos] = src[e];
        g_dstn[pos] = d;
        g_einv[pos] = 1.0f / (float)g_cnt[seg];   // cnt >= 1 (this edge exists)
    }
}

// ---------------- weight transpose: Wt[chunk][n][k] -------------------------
__global__ void k_transpose(const float* __restrict__ W, const float* __restrict__ root,
                            float* __restrict__ out, int O) {
    int idx = blockIdx.x*blockDim.x + threadIdx.x;
    int total = (RR+1)*O*DD;
    if (idx >= total) return;
    int chunk = idx / (O*DD);
    int rem   = idx - chunk*(O*DD);
    int n = rem / DD, k = rem - n*DD;
    float v = (chunk < RR) ? W[(size_t)chunk*DD*O + (size_t)k*O + n]
                           : root[(size_t)k*O + n];
    out[idx] = v;
}

// ---------------- fused aggregate + GEMM layer ------------------------------
__device__ __forceinline__ uint32_t f2tf(float x) {
    uint32_t r;
    asm("cvt.rna.tf32.f32 %0, %1;" : "=r"(r) : "f"(x));
    return r;
}

__device__ __forceinline__ void mma_tf32(float& c0, float& c1, float& c2, float& c3,
                                         uint32_t a0, uint32_t a1, uint32_t a2, uint32_t a3,
                                         uint32_t b0, uint32_t b1) {
    asm volatile(
        "mma.sync.aligned.m16n8k8.row.col.f32.tf32.tf32.f32 "
        "{%0,%1,%2,%3},{%4,%5,%6,%7},{%8,%9},{%0,%1,%2,%3};"
        : "+f"(c0), "+f"(c1), "+f"(c2), "+f"(c3)
        : "r"(a0), "r"(a1), "r"(a2), "r"(a3), "r"(b0), "r"(b1));
}

// CTA = 128 nodes x O outputs. For each of 9 chunks (8 relations + root):
//   phase A: zero sA; edge-parallel accumulate pre-scaled x rows via smem atomics
//   phase B: acc += A_chunk @ W_chunk   (tf32 mma.sync, fp32 accum; cvt at frag load)
template<int O, bool SIG>
__global__ void __launch_bounds__(256)
k_layer(const float* __restrict__ in,
        const float* __restrict__ Wt,     // [9][O][DD] pre-transposed
        const float* __restrict__ bias,
        float* __restrict__ out) {
    constexpr int TM = 128;
    constexpr int AP = DD + 4;
    constexpr int KP = DD + 4;

    extern __shared__ float smem[];
    float* sA  = smem;            // TM x AP (raw fp32)
    float* sBT = sA + TM*AP;      // O x KP  (n-major, tf32)

    const int tid  = threadIdx.x;
    const int lane = tid & 31;
    const int wid  = tid >> 5;
    const int tile = blockIdx.x * TM;

    float acc[O/8][4];
    #pragma unroll
    for (int n8 = 0; n8 < O/8; ++n8) {
        acc[n8][0] = 0.f; acc[n8][1] = 0.f; acc[n8][2] = 0.f; acc[n8][3] = 0.f;
    }

    const int g  = lane >> 2;
    const int tg = lane & 3;
    const int rbase = wid * 16;    // warp owns rows [rbase, rbase+16) in MMA

    for (int r = 0; r < RR + 1; ++r) {
        // ================= phase A =================
        if (r < RR) {
            // zero accumulation tile
            for (int idx = tid; idx < TM*AP/4; idx += 256)
                *reinterpret_cast<float4*>(sA + idx*4) = make_float4(0.f,0.f,0.f,0.f);
            // fill sBT (independent of sA zeroing)
            const float* Wp = Wt + (size_t)r*O*DD;
            for (int idx = tid; idx < O*DD; idx += 256) {
                int n = idx >> 7, k = idx & (DD-1);
                sBT[n*KP + k] = __uint_as_float(f2tf(Wp[idx]));
            }
            __syncthreads();

            // contiguous edge slice for (chunk r, this tile)
            const int lobase = r*NN + tile;
            const int lo = g_off[lobase];
            const int hiidx = r*NN + min(tile + TM, NN);
            const int hi = (hiidx < NRSEG) ? g_off[hiidx] : NE;

            // edge-parallel accumulation: warps stride the slice
            for (int e = lo + wid; e < hi; e += 8) {
                int   src = g_srcs[e];          // warp-uniform broadcast loads
                int   row = g_dstn[e] - tile;
                float iv  = g_einv[e];
                const float* xp = in + (size_t)src*DD + lane;
                float*       ap = sA + row*AP + lane;
                #pragma unroll
                for (int c = 0; c < 4; ++c) {
                    float v = __ldg(xp + 32*c) * iv;
                    atomicAdd(ap + 32*c, v);    // conflict-free banks (stride 32)
                }
            }
            __syncthreads();
        } else {
            // root chunk: direct copy of input tile (raw fp32)
            #pragma unroll
            for (int ii = 0; ii < 16; ++ii) {
                int node = tile + rbase + ii;
                float4 t = make_float4(0.f, 0.f, 0.f, 0.f);
                if (node < NN)
                    t = *reinterpret_cast<const float4*>(in + (size_t)node*DD + (lane << 2));
                *reinterpret_cast<float4*>(&sA[(rbase + ii)*AP + (lane << 2)]) = t;
            }
            const float* Wp = Wt + (size_t)RR*O*DD;
            for (int idx = tid; idx < O*DD; idx += 256) {
                int n = idx >> 7, k = idx & (DD-1);
                sBT[n*KP + k] = __uint_as_float(f2tf(Wp[idx]));
            }
            __syncthreads();
        }

        // ================= phase B: tf32 MMA (cvt.rna at A-fragment load) ====
        const int mrow = rbase;
        #pragma unroll
        for (int k8 = 0; k8 < DD/8; ++k8) {
            uint32_t a0 = f2tf(sA[(mrow + g    )*AP + k8*8 + tg    ]);
            uint32_t a1 = f2tf(sA[(mrow + g + 8)*AP + k8*8 + tg    ]);
            uint32_t a2 = f2tf(sA[(mrow + g    )*AP + k8*8 + tg + 4]);
            uint32_t a3 = f2tf(sA[(mrow + g + 8)*AP + k8*8 + tg + 4]);
            #pragma unroll
            for (int n8 = 0; n8 < O/8; ++n8) {
                uint32_t b0 = __float_as_uint(sBT[(n8*8 + g)*KP + k8*8 + tg    ]);
                uint32_t b1 = __float_as_uint(sBT[(n8*8 + g)*KP + k8*8 + tg + 4]);
                mma_tf32(acc[n8][0], acc[n8][1], acc[n8][2], acc[n8][3],
                         a0, a1, a2, a3, b0, b1);
            }
        }
        __syncthreads();
    }

    // ---- epilogue: bias (+ sigmoid), write out
    const int r0 = tile + rbase + g;
    const int r1 = r0 + 8;
    #pragma unroll
    for (int n8 = 0; n8 < O/8; ++n8) {
        int c0 = n8*8 + 2*tg;
        int c1 = c0 + 1;
        float bz0 = bias[c0], bz1 = bias[c1];
        float v00 = acc[n8][0] + bz0;
        float v01 = acc[n8][1] + bz1;
        float v10 = acc[n8][2] + bz0;
        float v11 = acc[n8][3] + bz1;
        if (SIG) {
            v00 = 1.f/(1.f + __expf(-v00));
            v01 = 1.f/(1.f + __expf(-v01));
            v10 = 1.f/(1.f + __expf(-v10));
            v11 = 1.f/(1.f + __expf(-v11));
        }
        if (r0 < NN) { out[(size_t)r0*O + c0] = v00; out[(size_t)r0*O + c1] = v01; }
        if (r1 < NN) { out[(size_t)r1*O + c0] = v10; out[(size_t)r1*O + c1] = v11; }
    }
}

// ---------------- launch ----------------------------------------------------
extern "C" void kernel_launch(void* const* d_in, const int* in_sizes, int n_in,
                              void* d_out, int out_size) {
    const float* x    = (const float*)d_in[0];
    const int*   esrc = (const int*)  d_in[1];
    const int*   edst = (const int*)  d_in[2];
    const int*   etyp = (const int*)  d_in[3];
    const float* W1   = (const float*)d_in[4];
    const float* r1   = (const float*)d_in[5];
    const float* b1   = (const float*)d_in[6];
    const float* W2   = (const float*)d_in[7];
    const float* r2   = (const float*)d_in[8];
    const float* b2   = (const float*)d_in[9];
    float* out = (float*)d_out;

    constexpr int SMEM_L1 = (128*(DD+4) + 128*(DD+4)) * 4;  // 135168
    constexpr int SMEM_L2 = (128*(DD+4) +  64*(DD+4)) * 4;  // 101376 -> 2 CTA/SM
    cudaFuncSetAttribute(k_layer<128,false>, cudaFuncAttributeMaxDynamicSharedMemorySize, SMEM_L1);
    cudaFuncSetAttribute(k_layer< 64,true >, cudaFuncAttributeMaxDynamicSharedMemorySize, SMEM_L2);

    void* p = nullptr;
    cudaGetSymbolAddress(&p, g_h);   float* h   = (float*)p;
    cudaGetSymbolAddress(&p, g_Wt1); float* wt1 = (float*)p;
    cudaGetSymbolAddress(&p, g_Wt2); float* wt2 = (float*)p;

    k_zero   <<<(NRSEG+255)/256, 256>>>();
    k_hist   <<<(NE+255)/256,    256>>>(edst, etyp);
    k_scan1  <<<NBLK,           1024>>>();
    k_scan2  <<<1,               512>>>();
    k_scan3  <<<(NRSEG+255)/256, 256>>>();
    k_scatter<<<(NE+255)/256,    256>>>(esrc, edst, etyp);

    k_transpose<<<((RR+1)*128*DD + 255)/256, 256>>>(W1, r1, wt1, 128);
    k_transpose<<<((RR+1)* 64*DD + 255)/256, 256>>>(W2, r2, wt2,  64);

    k_layer<128,false><<<(NN+127)/128, 256, SMEM_L1>>>(x, wt1, b1, h);
    k_layer< 64,true ><<<(NN+127)/128, 256, SMEM_L2>>>(h, wt2, b2, out);
}

// round 4
// speedup vs baseline: 2.4464x; 2.4464x over previous
#include <cuda_runtime.h>
#include <math.h>
#include <stdint.h>

#define NN 50000
#define NE 640000
#define RR 8
#define DD 128
#define NRSEG (NN*RR)
#define NBLK ((NRSEG + 1023)/1024)

// ---------------- scratch (device globals; no allocations allowed) ----------
__device__ int   g_cnt[NRSEG];
__device__ int   g_off[NRSEG];
__device__ int   g_cur[NRSEG];
__device__ int   g_bsum[NBLK];
__device__ int2  g_sd[NE];              // (src, dst) packed, CSR order
__device__ float g_h[NN*DD];
__device__ float g_Wt1[(RR+1)*DD*DD];   // [chunk][n][k], chunk 8 = root
__device__ float g_Wt2[(RR+1)*64*DD];

// ---------------- prelude: hist + weight transposes fused --------------------
// seg ordering is RELATION-MAJOR: seg = rel*NN + node, so each (warp-rows, rel)
// owns one contiguous edge slice sorted by dst.
__global__ void k_pre(const int* __restrict__ dst, const int* __restrict__ typ,
                      const float* __restrict__ W1, const float* __restrict__ r1,
                      const float* __restrict__ W2, const float* __restrict__ r2,
                      float* __restrict__ wt1, float* __restrict__ wt2) {
    const int HB = (NE + 255)/256;
    const int T1 = ((RR+1)*DD*DD + 255)/256;
    int b = blockIdx.x;
    if (b < HB) {
        int e = b*256 + threadIdx.x;
        if (e < NE) atomicAdd(&g_cnt[typ[e]*NN + dst[e]], 1);
    } else if (b < HB + T1) {
        int idx = (b - HB)*256 + threadIdx.x;
        if (idx < (RR+1)*DD*DD) {
            int chunk = idx / (DD*DD);
            int rem   = idx - chunk*(DD*DD);
            int n = rem >> 7, k = rem & 127;
            wt1[idx] = (chunk < RR) ? W1[(size_t)chunk*DD*DD + (size_t)k*DD + n]
                                    : r1[(size_t)k*DD + n];
        }
    } else {
        int idx = (b - HB - T1)*256 + threadIdx.x;
        if (idx < (RR+1)*64*DD) {
            int chunk = idx / (64*DD);
            int rem   = idx - chunk*(64*DD);
            int n = rem >> 7, k = rem & 127;
            wt2[idx] = (chunk < RR) ? W2[(size_t)chunk*DD*64 + (size_t)k*64 + n]
                                    : r2[(size_t)k*64 + n];
        }
    }
}

// ---------------- scans ------------------------------------------------------
__global__ void k_scan1() {
    __shared__ int s[1024];
    int tid = threadIdx.x;
    int i = blockIdx.x*1024 + tid;
    int v = (i < NRSEG) ? g_cnt[i] : 0;
    s[tid] = v; __syncthreads();
    for (int d = 1; d < 1024; d <<= 1) {
        int t = (tid >= d) ? s[tid-d] : 0;
        __syncthreads();
        s[tid] += t;
        __syncthreads();
    }
    if (i < NRSEG) g_off[i] = s[tid] - v;
    if (tid == 1023) g_bsum[blockIdx.x] = s[1023];
}

__global__ void k_scan2() {
    __shared__ int s[512];
    int tid = threadIdx.x;
    int v = (tid < NBLK) ? g_bsum[tid] : 0;
    s[tid] = v; __syncthreads();
    for (int d = 1; d < 512; d <<= 1) {
        int t = (tid >= d) ? s[tid-d] : 0;
        __syncthreads();
        s[tid] += t;
        __syncthreads();
    }
    if (tid < NBLK) g_bsum[tid] = s[tid] - v;
}

__global__ void k_scan3() {
    int i = blockIdx.x*blockDim.x + threadIdx.x;
    if (i < NRSEG) {
        int o = g_off[i] + g_bsum[i >> 10];
        g_off[i] = o;
        g_cur[i] = o;
    }
}

__global__ void k_scatter(const int* __restrict__ src, const int* __restrict__ dst,
                          const int* __restrict__ typ) {
    int e = blockIdx.x*blockDim.x + threadIdx.x;
    if (e < NE) {
        int d = dst[e];
        int seg = typ[e]*NN + d;
        int pos = atomicAdd(&g_cur[seg], 1);
        g_sd[pos] = make_int2(src[e], d);
    }
}

// ---------------- fused aggregate + GEMM layer ------------------------------
__device__ __forceinline__ uint32_t f2tf(float x) {
    uint32_t r;
    asm("cvt.rna.tf32.f32 %0, %1;" : "=r"(r) : "f"(x));
    return r;
}

__device__ __forceinline__ void mma_tf32(float& c0, float& c1, float& c2, float& c3,
                                         uint32_t a0, uint32_t a1, uint32_t a2, uint32_t a3,
                                         uint32_t b0, uint32_t b1) {
    asm volatile(
        "mma.sync.aligned.m16n8k8.row.col.f32.tf32.tf32.f32 "
        "{%0,%1,%2,%3},{%4,%5,%6,%7},{%8,%9},{%0,%1,%2,%3};"
        : "+f"(c0), "+f"(c1), "+f"(c2), "+f"(c3)
        : "r"(a0), "r"(a1), "r"(a2), "r"(a3), "r"(b0), "r"(b1));
}

// CTA = 256 nodes, 512 threads, 16 warps; warp owns 16 rows.
// Per chunk (8 relations + root):
//   gather: warp walks its contiguous, dst-sorted edge slice; register run-length
//           accumulate; flush (tf32) to own sA rows on row change. No atomics.
//   MMA:    acc += A_chunk @ W_chunk, tf32 mma.sync; B fragments pair-permuted
//           for single LDS.64 conflict-free loads.
template<int O, bool SIG>
__global__ void __launch_bounds__(512)
k_layer(const float* __restrict__ in,
        const float* __restrict__ Wt,     // [9][O][DD] pre-transposed [n][k]
        const float* __restrict__ bias,
        float* __restrict__ out) {
    constexpr int TM = 256;
    constexpr int NT = 512;
    constexpr int AP = DD + 4;    // sA row pitch
    constexpr int KP = DD + 8;    // sBp row pitch (permuted pairs, LDS.64 no-conflict)

    extern __shared__ float smem[];
    float* sA  = smem;            // TM x AP (tf32 bits)
    float* sBp = sA + TM*AP;      // O x KP  (pair-permuted k)

    const int tid  = threadIdx.x;
    const int lane = tid & 31;
    const int wid  = tid >> 5;
    const int tile = blockIdx.x * TM;

    float acc[O/8][4];
    #pragma unroll
    for (int n8 = 0; n8 < O/8; ++n8) {
        acc[n8][0] = 0.f; acc[n8][1] = 0.f; acc[n8][2] = 0.f; acc[n8][3] = 0.f;
    }

    const int g  = lane >> 2;
    const int tg = lane & 3;
    const int rbase = wid * 16;    // warp's row block

    for (int r = 0; r < RR + 1; ++r) {
        // ================= gather (own rows only; no cross-warp deps) ========
        if (r < RR) {
            #pragma unroll
            for (int i = 0; i < 16; ++i)
                *reinterpret_cast<float4*>(&sA[(rbase+i)*AP + (lane<<2)]) =
                    make_float4(0.f,0.f,0.f,0.f);

            int b0i = r*NN + min(tile + rbase,      NN);
            int b1i = r*NN + min(tile + rbase + 16, NN);
            int es = (b0i < NRSEG) ? g_off[b0i] : NE;
            int ee = (b1i < NRSEG) ? g_off[b1i] : NE;

            float4 v = make_float4(0.f,0.f,0.f,0.f);
            int c = 0, currow = -1;
            for (int e = es; e < ee; ++e) {
                int2 sd = g_sd[e];                 // warp-uniform broadcast
                if (sd.y != currow) {              // warp-uniform branch
                    if (c > 0) {
                        float inv = 1.f / (float)c;
                        float4 t;
                        t.x = __uint_as_float(f2tf(v.x * inv));
                        t.y = __uint_as_float(f2tf(v.y * inv));
                        t.z = __uint_as_float(f2tf(v.z * inv));
                        t.w = __uint_as_float(f2tf(v.w * inv));
                        *reinterpret_cast<float4*>(
                            &sA[(currow - tile)*AP + (lane<<2)]) = t;
                    }
                    v = make_float4(0.f,0.f,0.f,0.f);
                    c = 0;
                    currow = sd.y;
                }
                const float4 xv = *reinterpret_cast<const float4*>(
                    in + (size_t)sd.x*DD + (lane<<2));
                v.x += xv.x; v.y += xv.y; v.z += xv.z; v.w += xv.w;
                ++c;
            }
            if (c > 0) {
                float inv = 1.f / (float)c;
                float4 t;
                t.x = __uint_as_float(f2tf(v.x * inv));
                t.y = __uint_as_float(f2tf(v.y * inv));
                t.z = __uint_as_float(f2tf(v.z * inv));
                t.w = __uint_as_float(f2tf(v.w * inv));
                *reinterpret_cast<float4*>(&sA[(currow - tile)*AP + (lane<<2)]) = t;
            }
        } else {
            // root chunk: direct copy of input tile
            #pragma unroll
            for (int ii = 0; ii < 16; ++ii) {
                int node = tile + rbase + ii;
                float4 t = make_float4(0.f,0.f,0.f,0.f);
                if (node < NN) {
                    const float4 xv = *reinterpret_cast<const float4*>(
                        in + (size_t)node*DD + (lane<<2));
                    t.x = __uint_as_float(f2tf(xv.x));
                    t.y = __uint_as_float(f2tf(xv.y));
                    t.z = __uint_as_float(f2tf(xv.z));
                    t.w = __uint_as_float(f2tf(xv.w));
                }
                *reinterpret_cast<float4*>(&sA[(rbase + ii)*AP + (lane<<2)]) = t;
            }
        }
        __syncthreads();   // all prev-chunk MMA reads of sBp done

        // ---- fill sBp: pair-permute k within octets -> (tg, tg+4) adjacent
        {
            const float* Wp = Wt + (size_t)r*O*DD;
            for (int idx = tid; idx < O*DD; idx += NT) {
                int n = idx >> 7, k = idx & 127;
                int slot = (k & ~7) + ((k & 4) ? ((k & 3)*2 + 1) : ((k & 3)*2));
                sBp[n*KP + slot] = __uint_as_float(f2tf(Wp[idx]));
            }
        }
        __syncthreads();

        // ================= MMA =================
        #pragma unroll
        for (int k8 = 0; k8 < DD/8; ++k8) {
            uint32_t a0 = __float_as_uint(sA[(rbase + g    )*AP + k8*8 + tg    ]);
            uint32_t a1 = __float_as_uint(sA[(rbase + g + 8)*AP + k8*8 + tg    ]);
            uint32_t a2 = __float_as_uint(sA[(rbase + g    )*AP + k8*8 + tg + 4]);
            uint32_t a3 = __float_as_uint(sA[(rbase + g + 8)*AP + k8*8 + tg + 4]);
            #pragma unroll
            for (int n8 = 0; n8 < O/8; ++n8) {
                const float2 b = *reinterpret_cast<const float2*>(
                    &sBp[(n8*8 + g)*KP + k8*8 + tg*2]);
                mma_tf32(acc[n8][0], acc[n8][1], acc[n8][2], acc[n8][3],
                         a0, a1, a2, a3,
                         __float_as_uint(b.x), __float_as_uint(b.y));
            }
        }
    }

    // ---- epilogue: bias (+ sigmoid), write out
    const int r0 = tile + rbase + g;
    const int r1 = r0 + 8;
    #pragma unroll
    for (int n8 = 0; n8 < O/8; ++n8) {
        int c0 = n8*8 + 2*tg;
        int c1 = c0 + 1;
        float bz0 = bias[c0], bz1 = bias[c1];
        float v00 = acc[n8][0] + bz0;
        float v01 = acc[n8][1] + bz1;
        float v10 = acc[n8][2] + bz0;
        float v11 = acc[n8][3] + bz1;
        if (SIG) {
            v00 = 1.f/(1.f + __expf(-v00));
            v01 = 1.f/(1.f + __expf(-v01));
            v10 = 1.f/(1.f + __expf(-v10));
            v11 = 1.f/(1.f + __expf(-v11));
        }
        if (r0 < NN) { out[(size_t)r0*O + c0] = v00; out[(size_t)r0*O + c1] = v01; }
        if (r1 < NN) { out[(size_t)r1*O + c0] = v10; out[(size_t)r1*O + c1] = v11; }
    }
}

// ---------------- launch ----------------------------------------------------
extern "C" void kernel_launch(void* const* d_in, const int* in_sizes, int n_in,
                              void* d_out, int out_size) {
    const float* x    = (const float*)d_in[0];
    const int*   esrc = (const int*)  d_in[1];
    const int*   edst = (const int*)  d_in[2];
    const int*   etyp = (const int*)  d_in[3];
    const float* W1   = (const float*)d_in[4];
    const float* r1   = (const float*)d_in[5];
    const float* b1   = (const float*)d_in[6];
    const float* W2   = (const float*)d_in[7];
    const float* r2   = (const float*)d_in[8];
    const float* b2   = (const float*)d_in[9];
    float* out = (float*)d_out;

    constexpr int SMEM_L1 = (256*(DD+4) + 128*(DD+8)) * 4;  // 204800
    constexpr int SMEM_L2 = (256*(DD+4) +  64*(DD+8)) * 4;  // 169984
    cudaFuncSetAttribute(k_layer<128,false>, cudaFuncAttributeMaxDynamicSharedMemorySize, SMEM_L1);
    cudaFuncSetAttribute(k_layer< 64,true >, cudaFuncAttributeMaxDynamicSharedMemorySize, SMEM_L2);

    void* p = nullptr;
    cudaGetSymbolAddress(&p, g_h);   float* h    = (float*)p;
    cudaGetSymbolAddress(&p, g_Wt1); float* wt1  = (float*)p;
    cudaGetSymbolAddress(&p, g_Wt2); float* wt2  = (float*)p;
    cudaGetSymbolAddress(&p, g_cnt); int*   cntp = (int*)p;

    cudaMemsetAsync(cntp, 0, NRSEG*sizeof(int));

    const int HB = (NE + 255)/256;
    const int T1 = ((RR+1)*DD*DD + 255)/256;
    const int T2 = ((RR+1)*64*DD + 255)/256;
    k_pre    <<<HB + T1 + T2,    256>>>(edst, etyp, W1, r1, W2, r2, wt1, wt2);
    k_scan1  <<<NBLK,           1024>>>();
    k_scan2  <<<1,               512>>>();
    k_scan3  <<<(NRSEG+255)/256, 256>>>();
    k_scatter<<<(NE+255)/256,    256>>>(esrc, edst, etyp);

    k_layer<128,false><<<(NN+255)/256, 512, SMEM_L1>>>(x, wt1, b1, h);
    k_layer< 64,true ><<<(NN+255)/256, 512, SMEM_L2>>>(h, wt2, b2, out);
}

// round 5
// speedup vs baseline: 2.7801x; 1.1364x over previous
#include <cuda_runtime.h>
#include <math.h>
#include <stdint.h>

#define NN 50000
#define NE 640000
#define RR 8
#define DD 128
#define NRSEG (NN*RR)
#define NBLK ((NRSEG + 1023)/1024)

// ---------------- scratch (device globals; no allocations allowed) ----------
__device__ int   g_cnt[NRSEG];          // zero at load; self-zeroed by k_scatter
__device__ int   g_off[NRSEG];
__device__ int   g_cur[NRSEG];
__device__ int   g_bsum[NBLK];
__device__ int2  g_sd[NE];              // (src, dst) packed, CSR order
__device__ float g_h[NN*DD];
__device__ float g_Wt1[(RR+1)*DD*DD];   // [chunk][n][k], chunk 8 = root
__device__ float g_Wt2[(RR+1)*64*DD];

// ---------------- prelude: hist + weight transposes fused --------------------
// seg ordering is RELATION-MAJOR: seg = rel*NN + node, so each (warp-rows, rel)
// owns one contiguous edge slice sorted by dst.
__global__ void k_pre(const int* __restrict__ dst, const int* __restrict__ typ,
                      const float* __restrict__ W1, const float* __restrict__ r1,
                      const float* __restrict__ W2, const float* __restrict__ r2,
                      float* __restrict__ wt1, float* __restrict__ wt2) {
    const int HB = (NE + 255)/256;
    const int T1 = ((RR+1)*DD*DD + 255)/256;
    int b = blockIdx.x;
    if (b < HB) {
        int e = b*256 + threadIdx.x;
        if (e < NE) atomicAdd(&g_cnt[typ[e]*NN + dst[e]], 1);
    } else if (b < HB + T1) {
        int idx = (b - HB)*256 + threadIdx.x;
        if (idx < (RR+1)*DD*DD) {
            int chunk = idx / (DD*DD);
            int rem   = idx - chunk*(DD*DD);
            int n = rem >> 7, k = rem & 127;
            wt1[idx] = (chunk < RR) ? W1[(size_t)chunk*DD*DD + (size_t)k*DD + n]
                                    : r1[(size_t)k*DD + n];
        }
    } else {
        int idx = (b - HB - T1)*256 + threadIdx.x;
        if (idx < (RR+1)*64*DD) {
            int chunk = idx / (64*DD);
            int rem   = idx - chunk*(64*DD);
            int n = rem >> 7, k = rem & 127;
            wt2[idx] = (chunk < RR) ? W2[(size_t)chunk*DD*64 + (size_t)k*64 + n]
                                    : r2[(size_t)k*64 + n];
        }
    }
}

// ---------------- scans ------------------------------------------------------
__global__ void k_scan1() {
    __shared__ int s[1024];
    int tid = threadIdx.x;
    int i = blockIdx.x*1024 + tid;
    int v = (i < NRSEG) ? g_cnt[i] : 0;
    s[tid] = v; __syncthreads();
    for (int d = 1; d < 1024; d <<= 1) {
        int t = (tid >= d) ? s[tid-d] : 0;
        __syncthreads();
        s[tid] += t;
        __syncthreads();
    }
    if (i < NRSEG) g_off[i] = s[tid] - v;
    if (tid == 1023) g_bsum[blockIdx.x] = s[1023];
}

__global__ void k_scan2() {
    __shared__ int s[512];
    int tid = threadIdx.x;
    int v = (tid < NBLK) ? g_bsum[tid] : 0;
    s[tid] = v; __syncthreads();
    for (int d = 1; d < 512; d <<= 1) {
        int t = (tid >= d) ? s[tid-d] : 0;
        __syncthreads();
        s[tid] += t;
        __syncthreads();
    }
    if (tid < NBLK) g_bsum[tid] = s[tid] - v;
}

__global__ void k_scan3() {
    int i = blockIdx.x*blockDim.x + threadIdx.x;
    if (i < NRSEG) {
        int o = g_off[i] + g_bsum[i >> 10];
        g_off[i] = o;
        g_cur[i] = o;
    }
}

__global__ void k_scatter(const int* __restrict__ src, const int* __restrict__ dst,
                          const int* __restrict__ typ) {
    int e = blockIdx.x*blockDim.x + threadIdx.x;
    if (e < NE) {
        int d = dst[e];
        int seg = typ[e]*NN + d;
        int pos = atomicAdd(&g_cur[seg], 1);
        g_sd[pos] = make_int2(src[e], d);
    }
    // self-clean g_cnt for the next kernel_launch call (graph replay);
    // g_cnt is no longer read after the scans. NE >= NRSEG.
    if (e < NRSEG) g_cnt[e] = 0;
}

// ---------------- fused aggregate + GEMM layer ------------------------------
__device__ __forceinline__ uint32_t f2tf(float x) {
    uint32_t r;
    asm("cvt.rna.tf32.f32 %0, %1;" : "=r"(r) : "f"(x));
    return r;
}

__device__ __forceinline__ void mma_tf32(float& c0, float& c1, float& c2, float& c3,
                                         uint32_t a0, uint32_t a1, uint32_t a2, uint32_t a3,
                                         uint32_t b0, uint32_t b1) {
    asm volatile(
        "mma.sync.aligned.m16n8k8.row.col.f32.tf32.tf32.f32 "
        "{%0,%1,%2,%3},{%4,%5,%6,%7},{%8,%9},{%0,%1,%2,%3};"
        : "+f"(c0), "+f"(c1), "+f"(c2), "+f"(c3)
        : "r"(a0), "r"(a1), "r"(a2), "r"(a3), "r"(b0), "r"(b1));
}

// CTA = 256 nodes, 512 threads, 16 warps; warp owns 16 rows (private sA slice).
// Per chunk: {sync; fill sBp; sync; branch-free predicated gather; mma}.
template<int O, bool SIG>
__global__ void __launch_bounds__(512)
k_layer(const float* __restrict__ in,
        const float* __restrict__ Wt,     // [9][O][DD] pre-transposed [n][k]
        const float* __restrict__ bias,
        float* __restrict__ out) {
    constexpr int TM = 256;
    constexpr int NT = 512;
    constexpr int AP = DD + 4;    // sA row pitch
    constexpr int KP = DD + 8;    // sBp row pitch (pair-permuted, LDS.64 no-conflict)

    extern __shared__ float smem[];
    float* sA  = smem;            // TM x AP
    float* sBp = sA + TM*AP;      // O x KP

    const int tid  = threadIdx.x;
    const int lane = tid & 31;
    const int wid  = tid >> 5;
    const int tile = blockIdx.x * TM;

    float acc[O/8][4];
    #pragma unroll
    for (int n8 = 0; n8 < O/8; ++n8) {
        acc[n8][0] = 0.f; acc[n8][1] = 0.f; acc[n8][2] = 0.f; acc[n8][3] = 0.f;
    }

    const int g  = lane >> 2;
    const int tg = lane & 3;
    const int rbase = wid * 16;    // warp's private row block

    for (int r = 0; r < RR + 1; ++r) {
        __syncthreads();   // prev chunk's MMA done reading sBp
        // ---- fill sBp: pair-permute k within octets -> (tg, tg+4) adjacent
        {
            const float* Wp = Wt + (size_t)r*O*DD;
            for (int idx = tid; idx < O*DD; idx += NT) {
                int n = idx >> 7, k = idx & 127;
                int slot = (k & ~7) + ((k & 4) ? ((k & 3)*2 + 1) : ((k & 3)*2));
                sBp[n*KP + slot] = __uint_as_float(f2tf(Wp[idx]));
            }
        }
        __syncthreads();   // sBp ready

        // ================= gather (warp-private rows; no CTA barrier) ========
        if (r < RR) {
            #pragma unroll
            for (int i = 0; i < 16; ++i)
                *reinterpret_cast<float4*>(&sA[(rbase+i)*AP + (lane<<2)]) =
                    make_float4(0.f,0.f,0.f,0.f);

            // lane l (l<=16) holds boundary offset for row rbase+l
            int bidx = r*NN + min(tile + rbase + min(lane, 16), NN);
            int offv = (bidx < NRSEG) ? g_off[bidx] : NE;
            int es = __shfl_sync(0xffffffffu, offv, 0);
            int ee = __shfl_sync(0xffffffffu, offv, 16);

            // branch-free predicated run accumulate, unconditional overwrite STS
            float4 v = make_float4(0.f,0.f,0.f,0.f);
            int currow = -1;
            #pragma unroll 4
            for (int e = es; e < ee; ++e) {
                int2 sd = g_sd[e];                 // warp-uniform broadcast
                const float4 xv = *reinterpret_cast<const float4*>(
                    in + (size_t)sd.x*DD + (lane<<2));
                bool fresh = (sd.y != currow);
                currow = sd.y;
                v.x = (fresh ? 0.f : v.x) + xv.x;
                v.y = (fresh ? 0.f : v.y) + xv.y;
                v.z = (fresh ? 0.f : v.z) + xv.z;
                v.w = (fresh ? 0.f : v.w) + xv.w;
                *reinterpret_cast<float4*>(
                    &sA[(currow - tile)*AP + (lane<<2)]) = v;   // last write wins
            }

            // post-pass: scale rows by 1/cnt, convert to tf32 (thread-local cols)
            #pragma unroll
            for (int i = 0; i < 16; ++i) {
                int c = __shfl_sync(0xffffffffu, offv, i+1)
                      - __shfl_sync(0xffffffffu, offv, i);
                float inv = (c > 0) ? (1.f/(float)c) : 0.f;
                float4 t = *reinterpret_cast<float4*>(&sA[(rbase+i)*AP + (lane<<2)]);
                t.x = __uint_as_float(f2tf(t.x * inv));
                t.y = __uint_as_float(f2tf(t.y * inv));
                t.z = __uint_as_float(f2tf(t.z * inv));
                t.w = __uint_as_float(f2tf(t.w * inv));
                *reinterpret_cast<float4*>(&sA[(rbase+i)*AP + (lane<<2)]) = t;
            }
        } else {
            // root chunk: direct copy of input tile
            #pragma unroll
            for (int ii = 0; ii < 16; ++ii) {
                int node = tile + rbase + ii;
                float4 t = make_float4(0.f,0.f,0.f,0.f);
                if (node < NN) {
                    const float4 xv = *reinterpret_cast<const float4*>(
                        in + (size_t)node*DD + (lane<<2));
                    t.x = __uint_as_float(f2tf(xv.x));
                    t.y = __uint_as_float(f2tf(xv.y));
                    t.z = __uint_as_float(f2tf(xv.z));
                    t.w = __uint_as_float(f2tf(xv.w));
                }
                *reinterpret_cast<float4*>(&sA[(rbase + ii)*AP + (lane<<2)]) = t;
            }
        }
        __syncwarp();      // cross-lane sA reads in MMA below

        // ================= MMA =================
        #pragma unroll
        for (int k8 = 0; k8 < DD/8; ++k8) {
            uint32_t a0 = __float_as_uint(sA[(rbase + g    )*AP + k8*8 + tg    ]);
            uint32_t a1 = __float_as_uint(sA[(rbase + g + 8)*AP + k8*8 + tg    ]);
            uint32_t a2 = __float_as_uint(sA[(rbase + g    )*AP + k8*8 + tg + 4]);
            uint32_t a3 = __float_as_uint(sA[(rbase + g + 8)*AP + k8*8 + tg + 4]);
            #pragma unroll
            for (int n8 = 0; n8 < O/8; ++n8) {
                const float2 b = *reinterpret_cast<const float2*>(
                    &sBp[(n8*8 + g)*KP + k8*8 + tg*2]);
                mma_tf32(acc[n8][0], acc[n8][1], acc[n8][2], acc[n8][3],
                         a0, a1, a2, a3,
                         __float_as_uint(b.x), __float_as_uint(b.y));
            }
        }
    }

    // ---- epilogue: bias (+ sigmoid), write out
    const int r0 = tile + rbase + g;
    const int r1 = r0 + 8;
    #pragma unroll
    for (int n8 = 0; n8 < O/8; ++n8) {
        int c0 = n8*8 + 2*tg;
        int c1 = c0 + 1;
        float bz0 = bias[c0], bz1 = bias[c1];
        float v00 = acc[n8][0] + bz0;
        float v01 = acc[n8][1] + bz1;
        float v10 = acc[n8][2] + bz0;
        float v11 = acc[n8][3] + bz1;
        if (SIG) {
            v00 = 1.f/(1.f + __expf(-v00));
            v01 = 1.f/(1.f + __expf(-v01));
            v10 = 1.f/(1.f + __expf(-v10));
            v11 = 1.f/(1.f + __expf(-v11));
        }
        if (r0 < NN) { out[(size_t)r0*O + c0] = v00; out[(size_t)r0*O + c1] = v01; }
        if (r1 < NN) { out[(size_t)r1*O + c0] = v10; out[(size_t)r1*O + c1] = v11; }
    }
}

// ---------------- launch ----------------------------------------------------
extern "C" void kernel_launch(void* const* d_in, const int* in_sizes, int n_in,
                              void* d_out, int out_size) {
    const float* x    = (const float*)d_in[0];
    const int*   esrc = (const int*)  d_in[1];
    const int*   edst = (const int*)  d_in[2];
    const int*   etyp = (const int*)  d_in[3];
    const float* W1   = (const float*)d_in[4];
    const float* r1   = (const float*)d_in[5];
    const float* b1   = (const float*)d_in[6];
    const float* W2   = (const float*)d_in[7];
    const float* r2   = (const float*)d_in[8];
    const float* b2   = (const float*)d_in[9];
    float* out = (float*)d_out;

    constexpr int SMEM_L1 = (256*(DD+4) + 128*(DD+8)) * 4;  // 204800
    constexpr int SMEM_L2 = (256*(DD+4) +  64*(DD+8)) * 4;  // 169984
    cudaFuncSetAttribute(k_layer<128,false>, cudaFuncAttributeMaxDynamicSharedMemorySize, SMEM_L1);
    cudaFuncSetAttribute(k_layer< 64,true >, cudaFuncAttributeMaxDynamicSharedMemorySize, SMEM_L2);

    void* p = nullptr;
    cudaGetSymbolAddress(&p, g_h);   float* h    = (float*)p;
    cudaGetSymbolAddress(&p, g_Wt1); float* wt1  = (float*)p;
    cudaGetSymbolAddress(&p, g_Wt2); float* wt2  = (float*)p;

    const int HB = (NE + 255)/256;
    const int T1 = ((RR+1)*DD*DD + 255)/256;
    const int T2 = ((RR+1)*64*DD + 255)/256;
    k_pre    <<<HB + T1 + T2,    256>>>(edst, etyp, W1, r1, W2, r2, wt1, wt2);
    k_scan1  <<<NBLK,           1024>>>();
    k_scan2  <<<1,               512>>>();
    k_scan3  <<<(NRSEG+255)/256, 256>>>();
    k_scatter<<<(NE+255)/256,    256>>>(esrc, edst, etyp);

    k_layer<128,false><<<(NN+255)/256, 512, SMEM_L1>>>(x, wt1, b1, h);
    k_layer< 64,true ><<<(NN+255)/256, 512, SMEM_L2>>>(h, wt2, b2, out);
}

// round 7
// speedup vs baseline: 4.0855x; 1.4695x over previous
#include <cuda_runtime.h>
#include <cuda_fp16.h>
#include <math.h>
#include <stdint.h>

#define NN 50000
#define NE 640000
#define RR 8
#define DD 128
#define NRSEG (NN*RR)
#define NBLK ((NRSEG + 1023)/1024)

// ---------------- scratch (device globals; no allocations allowed) ----------
__device__ int    g_cnt[NRSEG];          // zero at load; self-zeroed by k_scatter
__device__ int    g_off[NRSEG];
__device__ int    g_cur[NRSEG];
__device__ int    g_bsum[NBLK];
__device__ int2   g_sd[NE];              // (src, dst) packed, CSR order
__device__ float  g_h[NN*DD];
__device__ __half g_W1h[(RR+1)*DD*DD];   // [chunk][n][k-permuted] half
__device__ __half g_W2h[(RR+1)*64*DD];

// k-permutation within each 16-group: slot order packs (2t,2t+1,2t+8,2t+9)
// adjacent so one LDS.64 yields both fp16-MMA fragments.
__device__ __forceinline__ int slot16(int c) {
    return ((c & 7) >> 1)*4 + (c & 1) + ((c & 8) >> 3)*2;
}

// ---------------- prelude: hist + weight cvt/permute fused -------------------
// seg ordering is RELATION-MAJOR: seg = rel*NN + node, so each (warp-rows, rel)
// owns one contiguous edge slice sorted by dst.
__global__ void k_pre(const int* __restrict__ dst, const int* __restrict__ typ,
                      const float* __restrict__ W1, const float* __restrict__ r1,
                      const float* __restrict__ W2, const float* __restrict__ r2) {
    const int HB = (NE + 255)/256;
    const int T1 = ((RR+1)*DD*DD + 255)/256;
    int b = blockIdx.x;
    if (b < HB) {
        int e = b*256 + threadIdx.x;
        if (e < NE) atomicAdd(&g_cnt[typ[e]*NN + dst[e]], 1);
    } else if (b < HB + T1) {
        int idx = (b - HB)*256 + threadIdx.x;
        if (idx < (RR+1)*DD*DD) {
            int chunk = idx / (DD*DD);
            int rem   = idx - chunk*(DD*DD);
            int n = rem >> 7, k = rem & 127;
            float v = (chunk < RR) ? W1[(size_t)chunk*DD*DD + (size_t)k*DD + n]
                                   : r1[(size_t)k*DD + n];
            g_W1h[(size_t)chunk*DD*DD + n*DD + (k & ~15) + slot16(k & 15)] =
                __float2half_rn(v);
        }
    } else {
        int idx = (b - HB - T1)*256 + threadIdx.x;
        if (idx < (RR+1)*64*DD) {
            int chunk = idx / (64*DD);
            int rem   = idx - chunk*(64*DD);
            int n = rem >> 7, k = rem & 127;
            float v = (chunk < RR) ? W2[(size_t)chunk*DD*64 + (size_t)k*64 + n]
                                   : r2[(size_t)k*64 + n];
            g_W2h[(size_t)chunk*64*DD + n*DD + (k & ~15) + slot16(k & 15)] =
                __float2half_rn(v);
        }
    }
}

// ---------------- scans ------------------------------------------------------
__global__ void k_scan1() {
    __shared__ int s[1024];
    int tid = threadIdx.x;
    int i = blockIdx.x*1024 + tid;
    int v = (i < NRSEG) ? g_cnt[i] : 0;
    s[tid] = v; __syncthreads();
    for (int d = 1; d < 1024; d <<= 1) {
        int t = (tid >= d) ? s[tid-d] : 0;
        __syncthreads();
        s[tid] += t;
        __syncthreads();
    }
    if (i < NRSEG) g_off[i] = s[tid] - v;
    if (tid == 1023) g_bsum[blockIdx.x] = s[1023];
}

__global__ void k_scan2() {
    __shared__ int s[512];
    int tid = threadIdx.x;
    int v = (tid < NBLK) ? g_bsum[tid] : 0;
    s[tid] = v; __syncthreads();
    for (int d = 1; d < 512; d <<= 1) {
        int t = (tid >= d) ? s[tid-d] : 0;
        __syncthreads();
        s[tid] += t;
        __syncthreads();
    }
    if (tid < NBLK) g_bsum[tid] = s[tid] - v;
}

__global__ void k_scan3() {
    int i = blockIdx.x*blockDim.x + threadIdx.x;
    if (i < NRSEG) {
        int o = g_off[i] + g_bsum[i >> 10];
        g_off[i] = o;
        g_cur[i] = o;
    }
}

__global__ void k_scatter(const int* __restrict__ src, const int* __restrict__ dst,
                          const int* __restrict__ typ) {
    int e = blockIdx.x*blockDim.x + threadIdx.x;
    if (e < NE) {
        int d = dst[e];
        int seg = typ[e]*NN + d;
        int pos = atomicAdd(&g_cur[seg], 1);
        g_sd[pos] = make_int2(src[e], d);
    }
    // self-clean g_cnt for the next graph replay (g_cnt unread after scans)
    if (e < NRSEG) g_cnt[e] = 0;
}

// ---------------- fused aggregate + GEMM layer (fp16 MMA) -------------------
__device__ __forceinline__ void mma_f16(float& c0, float& c1, float& c2, float& c3,
                                        uint32_t a0, uint32_t a1, uint32_t a2, uint32_t a3,
                                        uint32_t b0, uint32_t b1) {
    asm volatile(
        "mma.sync.aligned.m16n8k16.row.col.f32.f16.f16.f32 "
        "{%0,%1,%2,%3},{%4,%5,%6,%7},{%8,%9},{%0,%1,%2,%3};"
        : "+f"(c0), "+f"(c1), "+f"(c2), "+f"(c3)
        : "r"(a0), "r"(a1), "r"(a2), "r"(a3), "r"(b0), "r"(b1));
}

__device__ __forceinline__ uint32_t pack_h2(float x, float y) {
    __half2 h = __floats2half2_rn(x, y);
    return *reinterpret_cast<uint32_t*>(&h);
}
__device__ __forceinline__ float2 unpack_h2(uint32_t u) {
    __half2 h = *reinterpret_cast<__half2*>(&u);
    return __half22float2(h);
}

// CTA = 128 nodes, 256 threads, 8 warps; warp owns 16 rows (private sA slice).
// smem stored as half2 words, row pitch WP=72 words (stride ≡ 8 banks mod 32
// -> conflict-free LDS.64 fragment loads). k-permuted layout: one uint2 load
// yields (a0,a2)/(a1,a3)/(b0,b1) fragment pairs for m16n8k16.
template<int O, bool SIG>
__global__ void __launch_bounds__(256, 2)
k_layer(const float* __restrict__ in,
        const __half* __restrict__ Wh,    // [9][O][DD] half, k-permuted
        const float* __restrict__ bias,
        float* __restrict__ out) {
    constexpr int TM = 128;
    constexpr int NT = 256;
    constexpr int WP = 72;     // half2 words per row (64 data + 8 pad)

    extern __shared__ uint32_t smem[];
    uint32_t* sA = smem;           // TM * WP
    uint32_t* sB = smem + TM*WP;   // O  * WP

    const int tid  = threadIdx.x;
    const int lane = tid & 31;
    const int wid  = tid >> 5;
    const int tile = blockIdx.x * TM;

    float acc[O/8][4];
    #pragma unroll
    for (int n8 = 0; n8 < O/8; ++n8) {
        acc[n8][0] = 0.f; acc[n8][1] = 0.f; acc[n8][2] = 0.f; acc[n8][3] = 0.f;
    }

    const int g  = lane >> 2;
    const int tg = lane & 3;
    const int rbase = wid * 16;    // warp's private row block
    // lane's two half2 store slots (natural cols 4l..4l+3 under permutation)
    const int wbase = (lane >> 2)*8 + ((lane & 1) << 2) + ((lane & 2) >> 1);

    for (int r = 0; r < RR + 1; ++r) {
        __syncthreads();   // prev chunk's MMA done reading sB
        // ---- fill sB: pure half2 copy (pre-permuted in k_pre)
        {
            const uint32_t* Wp = reinterpret_cast<const uint32_t*>(
                Wh + (size_t)r*O*DD);
            #pragma unroll 4
            for (int idx = tid; idx < O*DD/2; idx += NT) {
                int n = idx >> 6, kk = idx & 63;
                sB[n*WP + kk] = Wp[idx];
            }
        }
        __syncthreads();   // sB ready

        // ================= gather (warp-private rows; no CTA barrier) ========
        if (r < RR) {
            // zero warp's 16 rows (contiguous block of 16*WP words)
            for (int w = lane; w < 16*WP; w += 32) sA[rbase*WP + w] = 0u;

            // lane l (l<=16) holds boundary offset for row rbase+l
            int bidx = r*NN + min(tile + rbase + min(lane, 16), NN);
            int offv = (bidx < NRSEG) ? g_off[bidx] : NE;
            int es = __shfl_sync(0xffffffffu, offv, 0);
            int ee = __shfl_sync(0xffffffffu, offv, 16);

            // branch-free predicated run accumulate, unconditional overwrite STS
            float4 v = make_float4(0.f,0.f,0.f,0.f);
            int currow = -1;
            #pragma unroll 4
            for (int e = es; e < ee; ++e) {
                int2 sd = g_sd[e];                 // warp-uniform broadcast
                const float4 xv = *reinterpret_cast<const float4*>(
                    in + (size_t)sd.x*DD + (lane<<2));
                bool fresh = (sd.y != currow);
                currow = sd.y;
                v.x = (fresh ? 0.f : v.x) + xv.x;
                v.y = (fresh ? 0.f : v.y) + xv.y;
                v.z = (fresh ? 0.f : v.z) + xv.z;
                v.w = (fresh ? 0.f : v.w) + xv.w;
                int rw = (currow - tile)*WP;
                sA[rw + wbase]     = pack_h2(v.x, v.y);   // last write wins
                sA[rw + wbase + 2] = pack_h2(v.z, v.w);
            }

            // post-pass: scale rows by 1/cnt (thread-local slots)
            #pragma unroll
            for (int i = 0; i < 16; ++i) {
                int c = __shfl_sync(0xffffffffu, offv, i+1)
                      - __shfl_sync(0xffffffffu, offv, i);
                if (c > 0) {
                    float inv = 1.f/(float)c;
                    int idx = (rbase+i)*WP + wbase;
                    float2 u0 = unpack_h2(sA[idx]);
                    float2 u1 = unpack_h2(sA[idx+2]);
                    sA[idx]   = pack_h2(u0.x*inv, u0.y*inv);
                    sA[idx+2] = pack_h2(u1.x*inv, u1.y*inv);
                }
            }
        } else {
            // root chunk: direct copy of input tile
            #pragma unroll
            for (int ii = 0; ii < 16; ++ii) {
                int node = tile + rbase + ii;
                float4 xv = make_float4(0.f,0.f,0.f,0.f);
                if (node < NN)
                    xv = *reinterpret_cast<const float4*>(
                        in + (size_t)node*DD + (lane<<2));
                int idx = (rbase+ii)*WP + wbase;
                sA[idx]   = pack_h2(xv.x, xv.y);
                sA[idx+2] = pack_h2(xv.z, xv.w);
            }
        }
        __syncwarp();      // cross-lane sA reads in MMA below

        // ================= MMA (fp16, fp32 accum) =================
        #pragma unroll
        for (int k16 = 0; k16 < DD/16; ++k16) {
            const uint2 aLo = *reinterpret_cast<const uint2*>(
                &sA[(rbase + g    )*WP + k16*8 + tg*2]);   // (a0, a2)
            const uint2 aHi = *reinterpret_cast<const uint2*>(
                &sA[(rbase + g + 8)*WP + k16*8 + tg*2]);   // (a1, a3)
            #pragma unroll
            for (int n8 = 0; n8 < O/8; ++n8) {
                const uint2 bb = *reinterpret_cast<const uint2*>(
                    &sB[(n8*8 + g)*WP + k16*8 + tg*2]);    // (b0, b1)
                mma_f16(acc[n8][0], acc[n8][1], acc[n8][2], acc[n8][3],
                        aLo.x, aHi.x, aLo.y, aHi.y, bb.x, bb.y);
            }
        }
    }

    // ---- epilogue: bias (+ sigmoid), write out
    const int r0 = tile + rbase + g;
    const int r1 = r0 + 8;
    #pragma unroll
    for (int n8 = 0; n8 < O/8; ++n8) {
        int c0 = n8*8 + 2*tg;
        int c1 = c0 + 1;
        float bz0 = bias[c0], bz1 = bias[c1];
        float v00 = acc[n8][0] + bz0;
        float v01 = acc[n8][1] + bz1;
        float v10 = acc[n8][2] + bz0;
        float v11 = acc[n8][3] + bz1;
        if (SIG) {
            v00 = 1.f/(1.f + __expf(-v00));
            v01 = 1.f/(1.f + __expf(-v01));
            v10 = 1.f/(1.f + __expf(-v10));
            v11 = 1.f/(1.f + __expf(-v11));
        }
        if (r0 < NN) { out[(size_t)r0*O + c0] = v00; out[(size_t)r0*O + c1] = v01; }
        if (r1 < NN) { out[(size_t)r1*O + c0] = v10; out[(size_t)r1*O + c1] = v11; }
    }
}

// ---------------- launch ----------------------------------------------------
extern "C" void kernel_launch(void* const* d_in, const int* in_sizes, int n_in,
                              void* d_out, int out_size) {
    const float* x    = (const float*)d_in[0];
    const int*   esrc = (const int*)  d_in[1];
    const int*   edst = (const int*)  d_in[2];
    const int*   etyp = (const int*)  d_in[3];
    const float* W1   = (const float*)d_in[4];
    const float* r1   = (const float*)d_in[5];
    const float* b1   = (const float*)d_in[6];
    const float* W2   = (const float*)d_in[7];
    const float* r2   = (const float*)d_in[8];
    const float* b2   = (const float*)d_in[9];
    float* out = (float*)d_out;

    constexpr int SMEM_L1 = (128 + 128) * 72 * 4;  // 73728 B -> 2 CTAs/SM
    constexpr int SMEM_L2 = (128 +  64) * 72 * 4;  // 55296 B -> 2 CTAs/SM
    cudaFuncSetAttribute(k_layer<128,false>, cudaFuncAttributeMaxDynamicSharedMemorySize, SMEM_L1);
    cudaFuncSetAttribute(k_layer< 64,true >, cudaFuncAttributeMaxDynamicSharedMemorySize, SMEM_L2);

    void* p = nullptr;
    cudaGetSymbolAddress(&p, g_h);   float*  h   = (float*)p;
    cudaGetSymbolAddress(&p, g_W1h); __half* w1h = (__half*)p;
    cudaGetSymbolAddress(&p, g_W2h); __half* w2h = (__half*)p;

    const int HB = (NE + 255)/256;
    const int T1 = ((RR+1)*DD*DD + 255)/256;
    const int T2 = ((RR+1)*64*DD + 255)/256;
    k_pre    <<<HB + T1 + T2,    256>>>(edst, etyp, W1, r1, W2, r2);
    k_scan1  <<<NBLK,           1024>>>();
    k_scan2  <<<1,               512>>>();
    k_scan3  <<<(NRSEG+255)/256, 256>>>();
    k_scatter<<<(NE+255)/256,    256>>>(esrc, edst, etyp);

    k_layer<128,false><<<(NN+127)/128, 256, SMEM_L1>>>(x, w1h, b1, h);
    k_layer< 64,true ><<<(NN+127)/128, 256, SMEM_L2>>>(h, w2h, b2, out);
}